// round 4
// baseline (speedup 1.0000x reference)
#include <cuda_runtime.h>
#include <cstdint>

#define NPART   100000
#define NFRAMES 500

// Scratch (no allocation allowed): per-frame keys, thresholds, rotate-multipliers.
__device__ uint2    g_keys[NFRAMES];
__device__ uint32_t g_thresh[2];
__device__ uint32_t g_rotmul[8];   // 2^r for r in {13,15,26,6,17,29,16,24}

// ---------------- plain threefry (setup only; perf-irrelevant) ----------------
__device__ __forceinline__ uint32_t rotl32(uint32_t x, int r) {
    return __funnelshift_l(x, x, r);
}
__device__ __forceinline__ void threefry_plain(uint32_t k0, uint32_t k1,
                                               uint32_t x0, uint32_t x1,
                                               uint32_t &o0, uint32_t &o1) {
    uint32_t ks2 = k0 ^ k1 ^ 0x1BD11BDAu;
    x0 += k0; x1 += k1;
#define RND(r) { x0 += x1; x1 = rotl32(x1, r); x1 ^= x0; }
    RND(13) RND(15) RND(26) RND(6)
    x0 += k1;  x1 += ks2 + 1u;
    RND(17) RND(29) RND(16) RND(24)
    x0 += ks2; x1 += k0 + 2u;
    RND(13) RND(15) RND(26) RND(6)
    x0 += k0;  x1 += k1 + 3u;
    RND(17) RND(29) RND(16) RND(24)
    x0 += k1;  x1 += ks2 + 4u;
    RND(13) RND(15) RND(26) RND(6)
    x0 += ks2; x1 += k0 + 5u;
#undef RND
    o0 = x0; o1 = x1;
}

// ceil-threshold: count of integers m with m * 2^-23 < X (exact pow2 scale).
__device__ __forceinline__ uint32_t thresh_from_prob(float p) {
    float X = p * 8388608.0f;
    uint32_t T = (uint32_t)X;
    if ((float)T < X) T++;
    return T;
}

__global__ void setup_kernel(const int* __restrict__ seed_ptr) {
    int tid = blockIdx.x * blockDim.x + threadIdx.x;
    long long seed = (long long)(*seed_ptr);
    uint32_t k0 = (uint32_t)(((unsigned long long)seed) >> 32);
    uint32_t k1 = (uint32_t)seed;

    // jax_threefry_partitionable: split(key,2) foldlike
    uint32_t kp0, kp1, ks0, ks1;
    threefry_plain(k0, k1, 0u, 0u, kp0, kp1);
    threefry_plain(k0, k1, 0u, 1u, ks0, ks1);

    if (tid < NFRAMES) {
        uint32_t o0, o1;
        threefry_plain(ks0, ks1, 0u, (uint32_t)tid, o0, o1);
        g_keys[tid] = make_uint2(o0, o1);
    }
    if (tid == 0) {
        uint32_t o0, o1;
        threefry_plain(kp0, kp1, 0u, 0u, o0, o1);
        uint32_t bits = o0 ^ o1;
        float u = __uint_as_float((bits >> 9) | 0x3f800000u) - 1.0f;
        float p = u * 0.001f;
        g_thresh[0] = thresh_from_prob(0.2f);
        g_thresh[1] = thresh_from_prob(p);
        const int rots[8] = {13, 15, 26, 6, 17, 29, 16, 24};
        for (int i = 0; i < 8; i++) g_rotmul[i] = 1u << rots[i];
    }
}

// ---------------- hot path: pipe-balanced threefry ----------------
// rotate via IMAD.WIDE (fma pipe): x * 2^r -> {hi = x>>(32-r), lo = x<<r};
// then one LOP3 computes (hi|lo)^x0 (immLut 0x56), absorbing the round xor.
__device__ __forceinline__ uint32_t mulrot_xor(uint32_t x, uint32_t pow2r, uint32_t x0) {
    uint64_t w;
    asm("mul.wide.u32 %0, %1, %2;" : "=l"(w) : "r"(x), "r"(pow2r));
    uint32_t lo = (uint32_t)w;
    uint32_t hi = (uint32_t)(w >> 32);
    uint32_t r;
    asm("lop3.b32 %0, %1, %2, %3, 0x56;" : "=r"(r) : "r"(hi), "r"(lo), "r"(x0));
    return r;
}

__global__ void __launch_bounds__(64)
hmm_kernel(const float* __restrict__ initial, float2* __restrict__ out) {
    int n = blockIdx.x * blockDim.x + threadIdx.x;
    if (n >= NPART) return;

    // runtime-valued multipliers: ptxas cannot strength-reduce back to SHF
    const uint32_t m13 = g_rotmul[0], m15 = g_rotmul[1], m26 = g_rotmul[2], m6  = g_rotmul[3];
    const uint32_t m17 = g_rotmul[4], m29 = g_rotmul[5], m16 = g_rotmul[6], m24 = g_rotmul[7];
    const uint32_t t0 = g_thresh[0];
    const uint32_t t1 = g_thresh[1];

    uint32_t s = (initial[2 * n + 1] > 0.5f) ? 1u : 0u;

    float2* optr = out + n;
    const uint32_t n2 = 2u * (uint32_t)n;

#pragma unroll 2
    for (int f = 0; f < NFRAMES; f++) {
        const uint2 key = __ldg(&g_keys[f]);
        const uint32_t k0 = key.x, k1 = key.y;
        const uint32_t ks2 = k0 ^ k1 ^ 0x1BD11BDAu;

        uint32_t x0 = 0u + k0;                 // counter hi = 0
        uint32_t x1 = (n2 + s) + k1;           // counter lo = 2n + s

#define RNDM(m) { x0 += x1; x1 = mulrot_xor(x1, m, x0); }
        RNDM(m13) RNDM(m15) RNDM(m26) RNDM(m6)
        x0 += k1;  x1 += ks2 + 1u;
        RNDM(m17) RNDM(m29) RNDM(m16) RNDM(m24)
        x0 += ks2; x1 += k0 + 2u;
        RNDM(m13) RNDM(m15) RNDM(m26) RNDM(m6)
        x0 += k0;  x1 += k1 + 3u;
        RNDM(m17) RNDM(m29) RNDM(m16) RNDM(m24)
        x0 += k1;  x1 += ks2 + 4u;
        RNDM(m13) RNDM(m15) RNDM(m26) RNDM(m6)
        x0 += ks2; x1 += k0 + 5u;
#undef RNDM

        uint32_t m = (x0 ^ x1) >> 9;           // folded draw -> 23-bit mantissa
        uint32_t th = s ? t1 : t0;
        s ^= (m < th) ? 1u : 0u;
        *optr = make_float2(s ? 0.0f : 1.0f, s ? 1.0f : 0.0f);
        optr += NPART;
    }
}

extern "C" void kernel_launch(void* const* d_in, const int* in_sizes, int n_in,
                              void* d_out, int out_size) {
    const float* initial = (const float*)d_in[0];
    const int*   seed    = (const int*)d_in[1];
    float2*      out     = (float2*)d_out;
    (void)in_sizes; (void)n_in; (void)out_size;

    setup_kernel<<<2, 256>>>(seed);
    int blocks = (NPART + 63) / 64;   // 1563 blocks of 64 threads
    hmm_kernel<<<blocks, 64>>>(initial, out);
}

// round 5
// speedup vs baseline: 1.3209x; 1.3209x over previous
#include <cuda_runtime.h>
#include <cstdint>

#define NPART   100000
#define NFRAMES 500

// Scratch (no allocation allowed): per-frame keys + integer flip thresholds.
__device__ uint2    g_keys[NFRAMES];
__device__ uint32_t g_thresh[2];

__device__ __forceinline__ uint32_t rotl32(uint32_t x, int r) {
    return __funnelshift_l(x, x, r);  // single SHF
}

// Exact threefry2x32 (20 rounds, 5 key injections).
__device__ __forceinline__ void threefry_plain(uint32_t k0, uint32_t k1,
                                               uint32_t x0, uint32_t x1,
                                               uint32_t &o0, uint32_t &o1) {
    uint32_t ks2 = k0 ^ k1 ^ 0x1BD11BDAu;
    x0 += k0; x1 += k1;
#define RND(r) { x0 += x1; x1 = rotl32(x1, r); x1 ^= x0; }
    RND(13) RND(15) RND(26) RND(6)
    x0 += k1;  x1 += ks2 + 1u;
    RND(17) RND(29) RND(16) RND(24)
    x0 += ks2; x1 += k0 + 2u;
    RND(13) RND(15) RND(26) RND(6)
    x0 += k0;  x1 += k1 + 3u;
    RND(17) RND(29) RND(16) RND(24)
    x0 += k1;  x1 += ks2 + 4u;
    RND(13) RND(15) RND(26) RND(6)
    x0 += ks2; x1 += k0 + 5u;
#undef RND
    o0 = x0; o1 = x1;
}

// ceil-threshold: count of integers m with m * 2^-23 < X (exact pow2 scale).
__device__ __forceinline__ uint32_t thresh_from_prob(float p) {
    float X = p * 8388608.0f;
    uint32_t T = (uint32_t)X;
    if ((float)T < X) T++;
    return T;
}

// jax_threefry_partitionable derivations (verified R3, rel_err = 0).
__global__ void setup_kernel(const int* __restrict__ seed_ptr) {
    int tid = blockIdx.x * blockDim.x + threadIdx.x;
    long long seed = (long long)(*seed_ptr);
    uint32_t k0 = (uint32_t)(((unsigned long long)seed) >> 32);
    uint32_t k1 = (uint32_t)seed;

    uint32_t kp0, kp1, ks0, ks1;
    threefry_plain(k0, k1, 0u, 0u, kp0, kp1);
    threefry_plain(k0, k1, 0u, 1u, ks0, ks1);

    if (tid < NFRAMES) {
        uint32_t o0, o1;
        threefry_plain(ks0, ks1, 0u, (uint32_t)tid, o0, o1);
        g_keys[tid] = make_uint2(o0, o1);
    }
    if (tid == 0) {
        uint32_t o0, o1;
        threefry_plain(kp0, kp1, 0u, 0u, o0, o1);
        uint32_t bits = o0 ^ o1;
        float u = __uint_as_float((bits >> 9) | 0x3f800000u) - 1.0f;
        float p = u * 0.001f;
        g_thresh[0] = thresh_from_prob(0.2f);
        g_thresh[1] = thresh_from_prob(p);
    }
}

// Hot path: 2 independent particles per thread (ILP=2), coalesced 16B stores.
__global__ void __launch_bounds__(128)
hmm_kernel(const float* __restrict__ initial, float4* __restrict__ out) {
    int t = blockIdx.x * blockDim.x + threadIdx.x;
    if (t >= NPART / 2) return;

    const uint32_t t0 = g_thresh[0];
    const uint32_t t1 = g_thresh[1];

    const int na = 2 * t;        // particle a
    // one-hot -> state bits
    uint32_t sa = (initial[2 * na + 1] > 0.5f) ? 1u : 0u;
    uint32_t sb = (initial[2 * na + 3] > 0.5f) ? 1u : 0u;

    const uint32_t ja_base = 4u * (uint32_t)t;        // 2*na
    const uint32_t jb_base = 4u * (uint32_t)t + 2u;   // 2*(na+1)

    float4* optr = out + t;      // out[f] row has NPART/2 float4 slots

#pragma unroll 2
    for (int f = 0; f < NFRAMES; f++) {
        const uint2 key = __ldg(&g_keys[f]);
        const uint32_t k0 = key.x, k1 = key.y;
        const uint32_t ks2 = k0 ^ k1 ^ 0x1BD11BDAu;

        // counters: (hi=0, lo=2n+s)
        uint32_t a0 = k0,                  a1 = (ja_base + sa) + k1;
        uint32_t b0 = k0,                  b1 = (jb_base + sb) + k1;

#define RND2(r) { a0 += a1; a1 = rotl32(a1, r) ^ a0; \
                  b0 += b1; b1 = rotl32(b1, r) ^ b0; }
#define INJ2(pa, pb, c) { a0 += (pa); a1 += (pb) + (c); \
                          b0 += (pa); b1 += (pb) + (c); }
        RND2(13) RND2(15) RND2(26) RND2(6)
        INJ2(k1, ks2, 1u)
        RND2(17) RND2(29) RND2(16) RND2(24)
        INJ2(ks2, k0, 2u)
        RND2(13) RND2(15) RND2(26) RND2(6)
        INJ2(k0, k1, 3u)
        RND2(17) RND2(29) RND2(16) RND2(24)
        INJ2(k1, ks2, 4u)
        RND2(13) RND2(15) RND2(26) RND2(6)
        INJ2(ks2, k0, 5u)
#undef RND2
#undef INJ2

        uint32_t ma = (a0 ^ a1) >> 9;      // folded draw -> 23-bit mantissa
        uint32_t mb = (b0 ^ b1) >> 9;
        sa ^= (ma < (sa ? t1 : t0)) ? 1u : 0u;
        sb ^= (mb < (sb ? t1 : t0)) ? 1u : 0u;

        *optr = make_float4(sa ? 0.0f : 1.0f, sa ? 1.0f : 0.0f,
                            sb ? 0.0f : 1.0f, sb ? 1.0f : 0.0f);
        optr += NPART / 2;                 // next frame
    }
}

extern "C" void kernel_launch(void* const* d_in, const int* in_sizes, int n_in,
                              void* d_out, int out_size) {
    const float* initial = (const float*)d_in[0];
    const int*   seed    = (const int*)d_in[1];
    float4*      out     = (float4*)d_out;
    (void)in_sizes; (void)n_in; (void)out_size;

    setup_kernel<<<2, 256>>>(seed);
    int threads_needed = NPART / 2;                    // 50000
    int blocks = (threads_needed + 127) / 128;         // 391
    hmm_kernel<<<blocks, 128>>>(initial, out);
}